// round 1
// baseline (speedup 1.0000x reference)
#include <cuda_runtime.h>
#include <cstddef>

// Problem constants
#define Bx   8
#define Nx   8192
#define Cx   128
#define Hx   8
#define DHx  64
#define Gx   32
#define HD   512           // H*DH
#define NCHUNK 64
#define CH_ROWS (Nx / NCHUNK)   // 128 rows per stage-1 block
#define LN_EPS 1e-5f

// ---------------------------------------------------------------------------
// Scratch (device globals; no runtime allocation allowed)
// ---------------------------------------------------------------------------
__device__ float g_Ypart[Bx][NCHUNK][Gx * Cx];   // 8 MB partial encode sums
__device__ float g_Y[Bx][Gx * Cx];               // Y[b,g,k] = sum_n x[b,n,k] * inv_in0[n,g]
__device__ float g_Spart[16][Gx];                // partial column sums of inv_in0
__device__ float g_Z[Bx][Hx][Gx * Cx];           // Z[b,h,g,m]
__device__ float g_Zs[Bx][Gx * Cx];              // sum over h of Z

// ---------------------------------------------------------------------------
// Stage 1: Y[b,g,k] = sum_n x[b,n,k] * inv_in[0,n,g]   (inv_in is head-broadcast)
// grid (NCHUNK, B), 256 threads. Each block reduces CH_ROWS rows of n.
// ---------------------------------------------------------------------------
__global__ __launch_bounds__(256) void k_stage1(const float* __restrict__ x,
                                                const float* __restrict__ inv_in)
{
    const int b = blockIdx.y, ch = blockIdx.x;
    const int t = threadIdx.x;
    const int n0 = ch * CH_ROWS;
    const int g  = t >> 3;            // 32 g values, 8 threads each
    const int k0 = (t & 7) * 16;      // 16 consecutive k per thread

    __shared__ __align__(16) float sx[8 * 128];  // 8 staged x rows
    __shared__ float sv[8 * 32];                 // 8 staged inv rows

    float acc[16];
#pragma unroll
    for (int i = 0; i < 16; i++) acc[i] = 0.f;

    const float* xb = x + (size_t)b * Nx * Cx;

    for (int i0 = 0; i0 < CH_ROWS; i0 += 8) {
        __syncthreads();
        const float* xrow = xb + (size_t)(n0 + i0) * Cx;   // 8*128 contiguous floats
#pragma unroll
        for (int j = 0; j < 4; j++) sx[t + j * 256] = xrow[t + j * 256];
        sv[t] = inv_in[(size_t)(n0 + i0 + (t >> 5)) * Gx + (t & 31)];
        __syncthreads();

#pragma unroll
        for (int r = 0; r < 8; r++) {
            const float iv = sv[r * 32 + g];
            const float4* sx4 = (const float4*)(sx + r * 128 + k0);
#pragma unroll
            for (int q = 0; q < 4; q++) {
                float4 xv = sx4[q];
                acc[q * 4 + 0] = fmaf(iv, xv.x, acc[q * 4 + 0]);
                acc[q * 4 + 1] = fmaf(iv, xv.y, acc[q * 4 + 1]);
                acc[q * 4 + 2] = fmaf(iv, xv.z, acc[q * 4 + 2]);
                acc[q * 4 + 3] = fmaf(iv, xv.w, acc[q * 4 + 3]);
            }
        }
    }

    float4* outp = (float4*)(&g_Ypart[b][ch][g * 128 + k0]);
#pragma unroll
    for (int q = 0; q < 4; q++)
        outp[q] = make_float4(acc[q * 4 + 0], acc[q * 4 + 1], acc[q * 4 + 2], acc[q * 4 + 3]);
}

// ---------------------------------------------------------------------------
// Partial column sums of inv_in0 (for the b_in bias term). grid 16, 256 thr.
// ---------------------------------------------------------------------------
__global__ __launch_bounds__(256) void k_spart(const float* __restrict__ inv_in)
{
    const int blk = blockIdx.x, t = threadIdx.x;
    const int g = t & 31, r = t >> 5;
    const int n0 = blk * 512;
    float acc = 0.f;
    for (int i = 0; i < 64; i++)
        acc += inv_in[(size_t)(n0 + r + i * 8) * Gx + g];
    __shared__ float sh[256];
    sh[t] = acc;
    __syncthreads();
    if (t < 32) {
        float s = 0.f;
#pragma unroll
        for (int rr = 0; rr < 8; rr++) s += sh[rr * 32 + t];
        g_Spart[blk][t] = s;
    }
}

// ---------------------------------------------------------------------------
// Reduce stage-1 partials. grid B, 256 threads.
// ---------------------------------------------------------------------------
__global__ __launch_bounds__(256) void k_reduceY()
{
    const int b = blockIdx.x, t = threadIdx.x;
#pragma unroll
    for (int j = 0; j < 4; j++) {
        const int idx4 = t + j * 256;
        float4 acc = make_float4(0.f, 0.f, 0.f, 0.f);
        for (int ch = 0; ch < NCHUNK; ch++) {
            float4 v = ((const float4*)g_Ypart[b][ch])[idx4];
            acc.x += v.x; acc.y += v.y; acc.z += v.z; acc.w += v.w;
        }
        ((float4*)g_Y[b])[idx4] = acc;
    }
}

// ---------------------------------------------------------------------------
// Middle: per (b,h):
//   spec[g,c]  = Y[b,g,:] @ W_in[:, h*64+c] + S[g]*b_in[h*64+c]
//   LN over (g,c), affine ln_g/ln_b
//   spec2      = specN @ mlp_w
//   Z[b,h,g,m] = spec2[g,:] @ W_out[h*64: , m]
// grid (H, B), 256 threads, 64 KB dynamic smem.
// ---------------------------------------------------------------------------
__global__ __launch_bounds__(256) void k_middle(const float* __restrict__ W_in,
                                                const float* __restrict__ b_in,
                                                const float* __restrict__ mlp_w,
                                                const float* __restrict__ ln_g,
                                                const float* __restrict__ ln_b,
                                                const float* __restrict__ W_out)
{
    extern __shared__ float sm[];
    float* sY = sm;            // 4096 : Y[b]  (32x128)
    float* sW = sm + 4096;     // 8192 : weight staging (reused 3x)
    float* sA = sm + 12288;    // 2048 : normalized spec
    float* sB = sm + 14336;    // 2048 : spec2

    __shared__ float sBin[64];
    __shared__ float sS[32];
    __shared__ float sRed[16];
    __shared__ float sStat[2];

    const int h = blockIdx.x, b = blockIdx.y;
    const int t = threadIdx.x;

#pragma unroll
    for (int j = 0; j < 16; j++) sY[t + j * 256] = g_Y[b][t + j * 256];
#pragma unroll
    for (int j = 0; j < 32; j++) {
        const int idx = t + j * 256;
        const int k = idx >> 6, c = idx & 63;
        sW[idx] = W_in[k * HD + h * DHx + c];
    }
    if (t < 64) sBin[t] = b_in[h * DHx + t];
    if (t < 32) {
        float s = 0.f;
#pragma unroll
        for (int i = 0; i < 16; i++) s += g_Spart[i][t];
        sS[t] = s;
    }
    __syncthreads();

    // spec: 8 outputs/thread, fixed c, g = g0 + 4j
    const int c = t & 63, g0 = t >> 6;
    float acc[8];
#pragma unroll
    for (int j = 0; j < 8; j++) acc[j] = 0.f;
    for (int k = 0; k < 128; k++) {
        const float w = sW[k * 64 + c];
#pragma unroll
        for (int j = 0; j < 8; j++)
            acc[j] = fmaf(sY[(g0 + 4 * j) * 128 + k], w, acc[j]);
    }
    float ls = 0.f, lss = 0.f;
#pragma unroll
    for (int j = 0; j < 8; j++) {
        acc[j] = fmaf(sS[g0 + 4 * j], sBin[c], acc[j]);
        ls += acc[j];
        lss = fmaf(acc[j], acc[j], lss);
    }
    // block reduce sum / sumsq over 2048 elements
#pragma unroll
    for (int o = 16; o; o >>= 1) {
        ls  += __shfl_xor_sync(0xffffffffu, ls,  o);
        lss += __shfl_xor_sync(0xffffffffu, lss, o);
    }
    if ((t & 31) == 0) { sRed[t >> 5] = ls; sRed[8 + (t >> 5)] = lss; }
    __syncthreads();
    if (t == 0) {
        float S = 0.f, SS = 0.f;
#pragma unroll
        for (int w = 0; w < 8; w++) { S += sRed[w]; SS += sRed[8 + w]; }
        const float mu  = S / 2048.f;
        const float var = SS / 2048.f - mu * mu;
        sStat[0] = mu;
        sStat[1] = rsqrtf(var + LN_EPS);
    }
    __syncthreads();
    const float mu = sStat[0], rs = sStat[1];
#pragma unroll
    for (int j = 0; j < 8; j++) {
        const int g = g0 + 4 * j;
        sA[g * 64 + c] = fmaf((acc[j] - mu) * rs, ln_g[g * 64 + c], ln_b[g * 64 + c]);
    }
    // stage mlp_w (64x64) into sW (spec-compute reads of sW finished above)
#pragma unroll
    for (int j = 0; j < 16; j++) sW[t + j * 256] = mlp_w[t + j * 256];
    __syncthreads();

    // spec2[g,o] = specN[g,:] @ mlp_w[:,o]
#pragma unroll
    for (int j = 0; j < 8; j++) acc[j] = 0.f;
    for (int i = 0; i < 64; i++) {
        const float w = sW[i * 64 + c];
#pragma unroll
        for (int j = 0; j < 8; j++)
            acc[j] = fmaf(sA[(g0 + 4 * j) * 64 + i], w, acc[j]);
    }
    __syncthreads();           // everyone done reading sW & sA
#pragma unroll
    for (int j = 0; j < 8; j++) sB[(g0 + 4 * j) * 64 + c] = acc[j];
    // stage W_out block (64x128) into sW
#pragma unroll
    for (int j = 0; j < 32; j++) {
        const int idx = t + j * 256;
        const int cc = idx >> 7, m = idx & 127;
        sW[idx] = W_out[(h * DHx + cc) * Cx + m];
    }
    __syncthreads();

    // Z[g,m] = spec2[g,:] @ W_out_block[:,m] : 16 outputs/thread
    const int m = t & 127, gz0 = t >> 7;
    float zacc[16];
#pragma unroll
    for (int j = 0; j < 16; j++) zacc[j] = 0.f;
    for (int cc = 0; cc < 64; cc++) {
        const float w = sW[cc * 128 + m];
#pragma unroll
        for (int j = 0; j < 16; j++)
            zacc[j] = fmaf(sB[(gz0 + 2 * j) * 64 + cc], w, zacc[j]);
    }
#pragma unroll
    for (int j = 0; j < 16; j++)
        g_Z[b][h][(gz0 + 2 * j) * 128 + m] = zacc[j];
}

// ---------------------------------------------------------------------------
// Sum Z over heads. grid B, 256 threads.
// ---------------------------------------------------------------------------
__global__ __launch_bounds__(256) void k_reduceZ()
{
    const int b = blockIdx.x, t = threadIdx.x;
#pragma unroll
    for (int j = 0; j < 4; j++) {
        const int idx4 = t + j * 256;
        float4 acc = make_float4(0.f, 0.f, 0.f, 0.f);
#pragma unroll
        for (int h = 0; h < Hx; h++) {
            float4 v = ((const float4*)g_Z[b][h])[idx4];
            acc.x += v.x; acc.y += v.y; acc.z += v.z; acc.w += v.w;
        }
        ((float4*)g_Zs[b])[idx4] = acc;
    }
}

// ---------------------------------------------------------------------------
// Stage 5: out[b,n,m] = b_out[m] + sum_g inv_out[0,n,g] * Zs[b,g,m]
// grid (32, B), 256 threads; each block does 256 n-rows.
// ---------------------------------------------------------------------------
__global__ __launch_bounds__(256) void k_stage5(const float* __restrict__ inv_out,
                                                const float* __restrict__ b_out,
                                                float* __restrict__ out)
{
    const int tile = blockIdx.x, b = blockIdx.y;
    const int t = threadIdx.x;
    __shared__ __align__(16) float sZ[4096];
    __shared__ float sBo[128];
    __shared__ float sIv[256];

#pragma unroll
    for (int j = 0; j < 16; j++) sZ[t + j * 256] = g_Zs[b][t + j * 256];
    if (t < 128) sBo[t] = b_out[t];

    const int n0 = tile * 256;
    const int lane = t & 31, r = t >> 5;
    const int m = lane * 4;
    float* outb = out + (size_t)b * Nx * Cx;

    for (int i = 0; i < 32; i++) {
        __syncthreads();
        sIv[t] = inv_out[(size_t)(n0 + i * 8 + (t >> 5)) * Gx + (t & 31)];
        __syncthreads();
        const int n = n0 + i * 8 + r;
        float a0 = sBo[m], a1 = sBo[m + 1], a2 = sBo[m + 2], a3 = sBo[m + 3];
#pragma unroll
        for (int g = 0; g < 32; g++) {
            const float iv = sIv[r * 32 + g];
            float4 z = ((const float4*)sZ)[g * 32 + lane];
            a0 = fmaf(iv, z.x, a0);
            a1 = fmaf(iv, z.y, a1);
            a2 = fmaf(iv, z.z, a2);
            a3 = fmaf(iv, z.w, a3);
        }
        ((float4*)(outb + (size_t)n * Cx))[lane] = make_float4(a0, a1, a2, a3);
    }
}

// ---------------------------------------------------------------------------
// Launch
// Inputs (metadata order): x, W_in, b_in, mlp_w, ln_g, ln_b, W_out, b_out,
//                          inv_in, inv_out. Output: float32 [B,N,C].
// ---------------------------------------------------------------------------
extern "C" void kernel_launch(void* const* d_in, const int* in_sizes, int n_in,
                              void* d_out, int out_size)
{
    const float* x      = (const float*)d_in[0];
    const float* W_in   = (const float*)d_in[1];
    const float* b_in   = (const float*)d_in[2];
    const float* mlp_w  = (const float*)d_in[3];
    const float* ln_g   = (const float*)d_in[4];
    const float* ln_b   = (const float*)d_in[5];
    const float* W_out  = (const float*)d_in[6];
    const float* b_out  = (const float*)d_in[7];
    const float* inv_in = (const float*)d_in[8];   // [H,N,G]; head slices identical -> use slice 0
    const float* inv_out= (const float*)d_in[9];
    float* out = (float*)d_out;

    cudaFuncSetAttribute(k_middle, cudaFuncAttributeMaxDynamicSharedMemorySize, 65536);

    k_stage1 <<<dim3(NCHUNK, Bx), 256>>>(x, inv_in);
    k_spart  <<<16, 256>>>(inv_in);
    k_reduceY<<<Bx, 256>>>();
    k_middle <<<dim3(Hx, Bx), 256, 65536>>>(W_in, b_in, mlp_w, ln_g, ln_b, W_out);
    k_reduceZ<<<Bx, 256>>>();
    k_stage5 <<<dim3(32, Bx), 256>>>(inv_out, b_out, out);
}

// round 2
// speedup vs baseline: 4.3070x; 4.3070x over previous
#include <cuda_runtime.h>
#include <cstddef>

#define Bx   8
#define Nx   8192
#define Cx   128
#define Hx   8
#define DHx  64
#define Gx   32
#define HD   512
#define LN_EPS 1e-5f

#define CHUNKS 32           // stage1/stage5 n-chunks
#define ROWS   256          // rows per chunk
#define STG    16           // stage1 rows per cp.async stage
#define NSTG   (ROWS / STG) // 16 stages

// ---------------------------------------------------------------------------
// Scratch
// ---------------------------------------------------------------------------
__device__ __align__(16) float g_Ypart[Bx][CHUNKS][Gx * Cx]; // 4 MB
__device__ __align__(16) float g_Y[Bx][Gx * Cx];
__device__ __align__(16) float g_Spart[CHUNKS][Gx];
__device__ __align__(16) float g_Z[Bx][Hx][Gx * Cx];
__device__ __align__(16) float g_Zs[Bx][Gx * Cx];

// ---------------------------------------------------------------------------
// Helpers: packed f32x2 FMA, cp.async
// ---------------------------------------------------------------------------
typedef unsigned long long ull;

__device__ __forceinline__ void fma2(ull& d, ull a, ull b) {
    asm("fma.rn.f32x2 %0, %1, %2, %0;" : "+l"(d) : "l"(a), "l"(b));
}
__device__ __forceinline__ ull dup2(float v) {
    ull r; asm("mov.b64 %0, {%1, %1};" : "=l"(r) : "f"(v)); return r;
}
__device__ __forceinline__ float2 unpk(ull v) {
    float2 f; asm("mov.b64 {%0, %1}, %2;" : "=f"(f.x), "=f"(f.y) : "l"(v)); return f;
}
__device__ __forceinline__ unsigned smem_u32(const void* p) {
    return (unsigned)__cvta_generic_to_shared(p);
}
__device__ __forceinline__ void cp16(unsigned dst, const void* src) {
    asm volatile("cp.async.cg.shared.global [%0], [%1], 16;" :: "r"(dst), "l"(src));
}
#define CP_COMMIT() asm volatile("cp.async.commit_group;")
#define CP_WAIT0()  asm volatile("cp.async.wait_group 0;")

// ---------------------------------------------------------------------------
// Stage 1: Ypart[b,ch,g,k] = sum_{n in chunk} x[b,n,k] * inv_in0[n,g]
// grid (CHUNKS, B), 128 threads. Thread: 8 g  x  4 k  (acc as 8x2 f32x2 pairs).
// Double-buffered cp.async staging of x rows + inv rows.
// ---------------------------------------------------------------------------
__global__ __launch_bounds__(128) void k_stage1(const float* __restrict__ x,
                                                const float* __restrict__ inv_in)
{
    __shared__ __align__(16) float sx[2][STG * 128];
    __shared__ __align__(16) float sv[2][STG * 32];

    const int b = blockIdx.y, ch = blockIdx.x;
    const int t = threadIdx.x;
    const int n0 = ch * ROWS;
    const int k0 = 4 * (t & 31);
    const int g0 = 8 * (t >> 5);

    const float* xb = x + (size_t)b * Nx * Cx + (size_t)n0 * Cx;
    const float* vb = inv_in + (size_t)n0 * Gx;

    const unsigned sxu[2] = { smem_u32(&sx[0][0]), smem_u32(&sx[1][0]) };
    const unsigned svu[2] = { smem_u32(&sv[0][0]), smem_u32(&sv[1][0]) };

    ull acc[8][2];
#pragma unroll
    for (int j = 0; j < 8; j++) { acc[j][0] = 0ull; acc[j][1] = 0ull; }

    // preload stage 0
#pragma unroll
    for (int j = 0; j < 4; j++) {
        const int cidx = t + 128 * j;
        cp16(sxu[0] + cidx * 16, xb + 4 * cidx);
    }
    cp16(svu[0] + t * 16, vb + 4 * t);
    CP_COMMIT();

    for (int s = 0; s < NSTG; s++) {
        CP_WAIT0();
        __syncthreads();
        if (s + 1 < NSTG) {
            const int nb = (s + 1) & 1;
            const float* xs = xb + (size_t)(s + 1) * STG * 128;
            const float* vs = vb + (size_t)(s + 1) * STG * 32;
#pragma unroll
            for (int j = 0; j < 4; j++) {
                const int cidx = t + 128 * j;
                cp16(sxu[nb] + cidx * 16, xs + 4 * cidx);
            }
            cp16(svu[nb] + t * 16, vs + 4 * t);
            CP_COMMIT();
        }
        const float* xsm = sx[s & 1];
        const float* vsm = sv[s & 1];
#pragma unroll
        for (int r = 0; r < STG; r++) {
            ulonglong2 xv = *(const ulonglong2*)&xsm[r * 128 + k0];
            float4 iva = *(const float4*)&vsm[r * 32 + g0];
            float4 ivb = *(const float4*)&vsm[r * 32 + g0 + 4];
            ull d;
            d = dup2(iva.x); fma2(acc[0][0], xv.x, d); fma2(acc[0][1], xv.y, d);
            d = dup2(iva.y); fma2(acc[1][0], xv.x, d); fma2(acc[1][1], xv.y, d);
            d = dup2(iva.z); fma2(acc[2][0], xv.x, d); fma2(acc[2][1], xv.y, d);
            d = dup2(iva.w); fma2(acc[3][0], xv.x, d); fma2(acc[3][1], xv.y, d);
            d = dup2(ivb.x); fma2(acc[4][0], xv.x, d); fma2(acc[4][1], xv.y, d);
            d = dup2(ivb.y); fma2(acc[5][0], xv.x, d); fma2(acc[5][1], xv.y, d);
            d = dup2(ivb.z); fma2(acc[6][0], xv.x, d); fma2(acc[6][1], xv.y, d);
            d = dup2(ivb.w); fma2(acc[7][0], xv.x, d); fma2(acc[7][1], xv.y, d);
        }
    }

    float* base = &g_Ypart[b][ch][0];
#pragma unroll
    for (int j = 0; j < 8; j++) {
        ulonglong2 o; o.x = acc[j][0]; o.y = acc[j][1];
        *(ulonglong2*)&base[(g0 + j) * 128 + k0] = o;
    }
}

// ---------------------------------------------------------------------------
// Column sums of inv_in0 per chunk. grid CHUNKS, 256 threads.
// ---------------------------------------------------------------------------
__global__ __launch_bounds__(256) void k_spart(const float* __restrict__ inv_in)
{
    const int ch = blockIdx.x, t = threadIdx.x;
    const int g = t & 31, r = t >> 5;
    const float* vb = inv_in + (size_t)ch * ROWS * Gx;
    float a = 0.f;
#pragma unroll 8
    for (int i = 0; i < 32; i++)
        a += vb[(r + 8 * i) * Gx + g];
    __shared__ float sh[256];
    sh[t] = a;
    __syncthreads();
    if (t < 32) {
        float s = 0.f;
#pragma unroll
        for (int rr = 0; rr < 8; rr++) s += sh[rr * 32 + t];
        g_Spart[ch][t] = s;
    }
}

// ---------------------------------------------------------------------------
// Reduce Y partials. grid (4, B), 256 threads — one float4 per thread.
// ---------------------------------------------------------------------------
__global__ __launch_bounds__(256) void k_reduceY()
{
    const int b = blockIdx.y;
    const int idx = blockIdx.x * 256 + threadIdx.x;   // 0..1023 float4
    float4 a = make_float4(0.f, 0.f, 0.f, 0.f);
#pragma unroll 8
    for (int ch = 0; ch < CHUNKS; ch++) {
        float4 v = ((const float4*)g_Ypart[b][ch])[idx];
        a.x += v.x; a.y += v.y; a.z += v.z; a.w += v.w;
    }
    ((float4*)g_Y[b])[idx] = a;
}

// ---------------------------------------------------------------------------
// Middle: per (b,h): spec = Y @ W_in_h + S*b_in ; LN(g,dh) ; @ mlp_w ; @ W_out_h
// grid (H, B), 256 threads, dynamic smem.
// All operands staged vectorized/transposed: data via LDS.64/.128,
// basis operand via warp-broadcast LDS.128.
// ---------------------------------------------------------------------------
__global__ __launch_bounds__(256) void k_middle(const float* __restrict__ W_in,
                                                const float* __restrict__ b_in,
                                                const float* __restrict__ mlp_w,
                                                const float* __restrict__ ln_g,
                                                const float* __restrict__ ln_b,
                                                const float* __restrict__ W_out)
{
    extern __shared__ __align__(16) float sm[];
    float* bufA = sm;                 // 8192 floats: W_in -> mlp_w -> W_out
    float* sYT  = sm + 8192;          // 4096: Y transposed [k][g]; reused as sBT
    float* sAT  = sm + 12288;         // 64*36 = 2304: normalized spec [c][g], pad 36

    __shared__ float sBin[64];
    __shared__ float sS[32];
    __shared__ float sRed[16];
    __shared__ float sStat[2];

    const int h = blockIdx.x, b = blockIdx.y;
    const int t = threadIdx.x;

    // stage Y transposed: sYT[k*32+g] = Y[g*128+k]
#pragma unroll
    for (int j = 0; j < 16; j++) {
        const int idx = t + 256 * j;
        const int k = idx >> 5, g = idx & 31;
        sYT[k * 32 + g] = g_Y[b][g * 128 + k];
    }
    // stage W_in slice [128][64] (vectorized)
#pragma unroll
    for (int j = 0; j < 8; j++) {
        const int idx = t + 256 * j;            // 0..2047 float4
        const int k = idx >> 4, c4 = idx & 15;
        ((float4*)bufA)[idx] = *(const float4*)&W_in[k * HD + h * DHx + 4 * c4];
    }
    if (t < 64) sBin[t] = b_in[h * DHx + t];
    if (t < 32) {
        float s = 0.f;
#pragma unroll
        for (int i = 0; i < CHUNKS; i++) s += g_Spart[i][t];
        sS[t] = s;
    }
    __syncthreads();

    // GEMM1: spec[g, c-pair]. thread: c0 = 2*(t&31), g0 = 4*(t>>5)
    const int c0 = 2 * (t & 31), g0 = 4 * (t >> 5);
    ull acc1[4] = {0ull, 0ull, 0ull, 0ull};
    for (int k = 0; k < 128; k++) {
        float4 y = *(const float4*)&sYT[k * 32 + g0];   // warp-broadcast
        ull w = *(const ull*)&bufA[k * 64 + c0];
        fma2(acc1[0], w, dup2(y.x));
        fma2(acc1[1], w, dup2(y.y));
        fma2(acc1[2], w, dup2(y.z));
        fma2(acc1[3], w, dup2(y.w));
    }
    {
        ull bp = *(const ull*)&sBin[c0];
#pragma unroll
        for (int j = 0; j < 4; j++) fma2(acc1[j], bp, dup2(sS[g0 + j]));
    }
    // LN stats over 2048 values
    float ls = 0.f, lss = 0.f;
#pragma unroll
    for (int j = 0; j < 4; j++) {
        float2 p = unpk(acc1[j]);
        ls += p.x + p.y;
        lss = fmaf(p.x, p.x, lss); lss = fmaf(p.y, p.y, lss);
    }
#pragma unroll
    for (int o = 16; o; o >>= 1) {
        ls  += __shfl_xor_sync(0xffffffffu, ls,  o);
        lss += __shfl_xor_sync(0xffffffffu, lss, o);
    }
    if ((t & 31) == 0) { sRed[t >> 5] = ls; sRed[8 + (t >> 5)] = lss; }
    __syncthreads();
    if (t == 0) {
        float S = 0.f, SS = 0.f;
#pragma unroll
        for (int w = 0; w < 8; w++) { S += sRed[w]; SS += sRed[8 + w]; }
        const float mu = S / 2048.f;
        sStat[0] = mu;
        sStat[1] = rsqrtf(SS / 2048.f - mu * mu + LN_EPS);
    }
    __syncthreads();
    const float mu = sStat[0], rs = sStat[1];
    // normalize + affine -> sAT[c][g] (stride 36)
#pragma unroll
    for (int j = 0; j < 4; j++) {
        const int g = g0 + j;
        float2 p  = unpk(acc1[j]);
        float2 gg = *(const float2*)&ln_g[g * 64 + c0];
        float2 bb = *(const float2*)&ln_b[g * 64 + c0];
        sAT[c0 * 36 + g]       = fmaf((p.x - mu) * rs, gg.x, bb.x);
        sAT[(c0 + 1) * 36 + g] = fmaf((p.y - mu) * rs, gg.y, bb.y);
    }
    // stage mlp_w [64][64]
#pragma unroll
    for (int j = 0; j < 4; j++) {
        const int idx = t + 256 * j;
        ((float4*)bufA)[idx] = ((const float4*)mlp_w)[idx];
    }
    __syncthreads();

    // GEMM2: spec2[g, o-pair] ; o0 = c0
    ull acc2[4] = {0ull, 0ull, 0ull, 0ull};
    for (int i = 0; i < 64; i++) {
        float4 a = *(const float4*)&sAT[i * 36 + g0];   // warp-broadcast
        ull w = *(const ull*)&bufA[i * 64 + c0];
        fma2(acc2[0], w, dup2(a.x));
        fma2(acc2[1], w, dup2(a.y));
        fma2(acc2[2], w, dup2(a.z));
        fma2(acc2[3], w, dup2(a.w));
    }
    __syncthreads();   // sAT reads + sYT (GEMM1) reads complete

    float* sBT = sYT;  // reuse as spec2 transposed [o][g], stride 36
#pragma unroll
    for (int j = 0; j < 4; j++) {
        float2 p = unpk(acc2[j]);
        sBT[c0 * 36 + (g0 + j)]       = p.x;
        sBT[(c0 + 1) * 36 + (g0 + j)] = p.y;
    }
    // stage W_out block [64][128]
#pragma unroll
    for (int j = 0; j < 8; j++) {
        const int idx = t + 256 * j;            // 0..2047 float4
        const int cc = idx >> 5, m4 = idx & 31;
        ((float4*)bufA)[idx] = *(const float4*)&W_out[(h * DHx + cc) * Cx + 4 * m4];
    }
    __syncthreads();

    // GEMM3: Z[g, m-pair]. thread: m0 = 2*(t&63), g8 = 8*(t>>6)
    const int m0 = 2 * (t & 63), g8 = 8 * (t >> 6);
    ull acc3[8];
#pragma unroll
    for (int j = 0; j < 8; j++) acc3[j] = 0ull;
    for (int cc = 0; cc < 64; cc++) {
        float4 b0 = *(const float4*)&sBT[cc * 36 + g8];      // warp-broadcast
        float4 b1 = *(const float4*)&sBT[cc * 36 + g8 + 4];
        ull w = *(const ull*)&bufA[cc * 128 + m0];
        fma2(acc3[0], w, dup2(b0.x));
        fma2(acc3[1], w, dup2(b0.y));
        fma2(acc3[2], w, dup2(b0.z));
        fma2(acc3[3], w, dup2(b0.w));
        fma2(acc3[4], w, dup2(b1.x));
        fma2(acc3[5], w, dup2(b1.y));
        fma2(acc3[6], w, dup2(b1.z));
        fma2(acc3[7], w, dup2(b1.w));
    }
#pragma unroll
    for (int j = 0; j < 8; j++)
        *(ull*)&g_Z[b][h][(g8 + j) * 128 + m0] = acc3[j];
}

// ---------------------------------------------------------------------------
// Sum Z over heads. grid (4, B), 256 threads.
// ---------------------------------------------------------------------------
__global__ __launch_bounds__(256) void k_reduceZ()
{
    const int b = blockIdx.y;
    const int idx = blockIdx.x * 256 + threadIdx.x;
    float4 a = make_float4(0.f, 0.f, 0.f, 0.f);
#pragma unroll
    for (int h = 0; h < Hx; h++) {
        float4 v = ((const float4*)g_Z[b][h])[idx];
        a.x += v.x; a.y += v.y; a.z += v.z; a.w += v.w;
    }
    ((float4*)g_Zs[b])[idx] = a;
}

// ---------------------------------------------------------------------------
// Stage 5: out[b,n,m] = b_out[m] + sum_g inv_out0[n,g] * Zs[b,g,m]
// grid (CHUNKS, B), 128 threads. Thread: 8 n x 4 m per pass, 8 passes.
// ---------------------------------------------------------------------------
__global__ __launch_bounds__(128) void k_stage5(const float* __restrict__ inv_out,
                                                const float* __restrict__ b_out,
                                                float* __restrict__ out)
{
    extern __shared__ __align__(16) float sm5[];
    float* sZ  = sm5;            // 4096
    float* sIv = sm5 + 4096;     // 8192 : iv rows for this chunk
    __shared__ float sBo[128];

    const int ch = blockIdx.x, b = blockIdx.y;
    const int t = threadIdx.x;
    const int n0 = ch * ROWS;
    const int m0 = 4 * (t & 31);
    const int nq = t >> 5;

#pragma unroll
    for (int j = 0; j < 8; j++) {
        const int idx = t + 128 * j;
        ((float4*)sZ)[idx] = ((const float4*)g_Zs[b])[idx];
    }
    const float4* ivsrc = (const float4*)(inv_out + (size_t)n0 * Gx);
#pragma unroll
    for (int j = 0; j < 16; j++) {
        const int idx = t + 128 * j;
        ((float4*)sIv)[idx] = ivsrc[idx];
    }
    sBo[t] = b_out[t];
    __syncthreads();

    const ull bi0 = *(const ull*)&sBo[m0];
    const ull bi1 = *(const ull*)&sBo[m0 + 2];
    float* outb = out + (size_t)b * Nx * Cx;

    for (int pass = 0; pass < 8; pass++) {
        const int rbase = pass * 32 + nq * 8;
        ull acc[8][2];
#pragma unroll
        for (int r = 0; r < 8; r++) { acc[r][0] = bi0; acc[r][1] = bi1; }

#pragma unroll
        for (int gq = 0; gq < 8; gq++) {
            const int g0 = 4 * gq;
            ull zx[4], zy[4];
#pragma unroll
            for (int q = 0; q < 4; q++) {
                ulonglong2 zz = *(const ulonglong2*)&sZ[(g0 + q) * 128 + m0];
                zx[q] = zz.x; zy[q] = zz.y;
            }
#pragma unroll
            for (int r = 0; r < 8; r++) {
                float4 iv = *(const float4*)&sIv[(rbase + r) * 32 + g0]; // warp-broadcast
                ull d;
                d = dup2(iv.x); fma2(acc[r][0], zx[0], d); fma2(acc[r][1], zy[0], d);
                d = dup2(iv.y); fma2(acc[r][0], zx[1], d); fma2(acc[r][1], zy[1], d);
                d = dup2(iv.z); fma2(acc[r][0], zx[2], d); fma2(acc[r][1], zy[2], d);
                d = dup2(iv.w); fma2(acc[r][0], zx[3], d); fma2(acc[r][1], zy[3], d);
            }
        }
#pragma unroll
        for (int r = 0; r < 8; r++) {
            ulonglong2 o; o.x = acc[r][0]; o.y = acc[r][1];
            *(ulonglong2*)&outb[(size_t)(n0 + rbase + r) * Cx + m0] = o;
        }
    }
}

// ---------------------------------------------------------------------------
// Launch. Inputs: x, W_in, b_in, mlp_w, ln_g, ln_b, W_out, b_out, inv_in, inv_out
// ---------------------------------------------------------------------------
extern "C" void kernel_launch(void* const* d_in, const int* in_sizes, int n_in,
                              void* d_out, int out_size)
{
    const float* x      = (const float*)d_in[0];
    const float* W_in   = (const float*)d_in[1];
    const float* b_in   = (const float*)d_in[2];
    const float* mlp_w  = (const float*)d_in[3];
    const float* ln_g   = (const float*)d_in[4];
    const float* ln_b   = (const float*)d_in[5];
    const float* W_out  = (const float*)d_in[6];
    const float* b_out  = (const float*)d_in[7];
    const float* inv_in = (const float*)d_in[8];   // head-broadcast: use slice 0
    const float* inv_out= (const float*)d_in[9];
    float* out = (float*)d_out;

    const int mid_smem = (8192 + 4096 + 64 * 36) * 4;   // 58368 B
    const int s5_smem  = (4096 + 8192) * 4;             // 49152 B
    cudaFuncSetAttribute(k_middle, cudaFuncAttributeMaxDynamicSharedMemorySize, mid_smem);
    cudaFuncSetAttribute(k_stage5, cudaFuncAttributeMaxDynamicSharedMemorySize, s5_smem);

    k_stage1 <<<dim3(CHUNKS, Bx), 128>>>(x, inv_in);
    k_spart  <<<CHUNKS, 256>>>(inv_in);
    k_reduceY<<<dim3(4, Bx), 256>>>();
    k_middle <<<dim3(Hx, Bx), 256, mid_smem>>>(W_in, b_in, mlp_w, ln_g, ln_b, W_out);
    k_reduceZ<<<dim3(4, Bx), 256>>>();
    k_stage5 <<<dim3(CHUNKS, Bx), 128, s5_smem>>>(inv_out, b_out, out);
}